// round 1
// baseline (speedup 1.0000x reference)
#include <cuda_runtime.h>
#include <math.h>

// Problem constants (B=4, C=3=heads, c_h=1, H=W=64, N=4096, scale = c_h^-0.5 = 1)
#define BATCH 4
#define CH 3
#define NPIX 4096
#define NBH (BATCH * CH)
#define LOG2E 1.4426950408889634f

// Scratch (device globals — no allocation allowed)
__device__ float  g_q[NBH * NPIX];           // gated q, per (b,h)
__device__ float2 g_kv[NBH * NPIX];          // (k * log2e, v) interleaved
__device__ float  g_att[NBH * NPIX];         // attention output per head

__device__ __forceinline__ float ex2f(float x) {
    float y;
    asm("ex2.approx.f32 %0, %1;" : "=f"(y) : "f"(x));
    return y;
}

// ---------------- Kernel A: luma gate + 1x1 convs ----------------
__device__ __forceinline__ float block_sum_1024(float v) {
    __shared__ float sh[32];
    #pragma unroll
    for (int o = 16; o; o >>= 1) v += __shfl_down_sync(0xFFFFFFFFu, v, o);
    int lane = threadIdx.x & 31, w = threadIdx.x >> 5;
    if (lane == 0) sh[w] = v;
    __syncthreads();
    if (w == 0) {
        float r = sh[lane];
        #pragma unroll
        for (int o = 16; o; o >>= 1) r += __shfl_down_sync(0xFFFFFFFFu, r, o);
        if (lane == 0) sh[0] = r;
    }
    __syncthreads();
    float r = sh[0];
    __syncthreads();
    return r;
}

__global__ void __launch_bounds__(1024) prep_kernel(
    const float* __restrict__ rgb,
    const float* __restrict__ wq,
    const float* __restrict__ wk,
    const float* __restrict__ wv)
{
    const int b = blockIdx.x;
    const int t = threadIdx.x;
    const float* base = rgb + (size_t)b * CH * NPIX;

    float rr[4], gg[4], bb[4], L[4];
    float sL = 0.f;
    #pragma unroll
    for (int i = 0; i < 4; i++) {
        int n = t + i * 1024;
        rr[i] = base[n];
        gg[i] = base[NPIX + n];
        bb[i] = base[2 * NPIX + n];
        L[i] = 0.299f * rr[i] + 0.587f * gg[i] + 0.114f * bb[i];
        sL += L[i];
    }
    float mu = block_sum_1024(sL) * (1.0f / NPIX);

    float d[4], s1 = 0.f, s2 = 0.f;
    #pragma unroll
    for (int i = 0; i < 4; i++) {
        d[i] = fabsf(L[i] - mu);
        s1 += d[i];
        s2 += d[i] * d[i];
    }
    float S1 = block_sum_1024(s1);
    float S2 = block_sum_1024(s2);
    float var = (S2 - S1 * S1 * (1.0f / NPIX)) * (1.0f / (NPIX - 1));
    float stdv = sqrtf(fmaxf(var, 0.f)) + 1e-6f;
    float inv_std = 1.0f / stdv;

    // weights: [o, i] row-major, 9 floats each
    float Wq[9], Wk[9], Wv[9];
    #pragma unroll
    for (int j = 0; j < 9; j++) { Wq[j] = wq[j]; Wk[j] = wk[j]; Wv[j] = wv[j]; }

    #pragma unroll
    for (int i = 0; i < 4; i++) {
        int n = t + i * 1024;
        float x = d[i] * inv_std;
        float gate = 1.0f / (1.0f + ex2f(-x * LOG2E));   // sigmoid
        float gf = 1.0f + gate;
        #pragma unroll
        for (int c = 0; c < 3; c++) {
            float q = (Wq[3 * c] * rr[i] + Wq[3 * c + 1] * gg[i] + Wq[3 * c + 2] * bb[i]) * gf;
            float k = (Wk[3 * c] * rr[i] + Wk[3 * c + 1] * gg[i] + Wk[3 * c + 2] * bb[i]);
            float v = (Wv[3 * c] * rr[i] + Wv[3 * c + 1] * gg[i] + Wv[3 * c + 2] * bb[i]);
            int idx = (b * CH + c) * NPIX + n;
            g_q[idx] = q;
            g_kv[idx] = make_float2(k * LOG2E, v);
        }
    }
}

// ---------------- Kernel B: streaming softmax-attention per (b,h) ----------------
// grid: (NPIX/128, 12), block: 128 threads; each thread owns one row n.
__global__ void __launch_bounds__(128) attn_kernel()
{
    __shared__ float2 s_kv[NPIX];      // 32 KB
    __shared__ float  sred[8];

    const int bh = blockIdx.y;
    const int t = threadIdx.x;
    const float2* kv = g_kv + (size_t)bh * NPIX;

    // Stage k,v into SMEM + track min/max of k (log2-scaled)
    float kmx = -1e30f, kmn = 1e30f;
    #pragma unroll
    for (int i = t; i < NPIX; i += 128) {
        float2 x = kv[i];
        s_kv[i] = x;
        kmx = fmaxf(kmx, x.x);
        kmn = fminf(kmn, x.x);
    }
    int lane = t & 31, w = t >> 5;
    #pragma unroll
    for (int o = 16; o; o >>= 1) {
        kmx = fmaxf(kmx, __shfl_down_sync(0xFFFFFFFFu, kmx, o));
        kmn = fminf(kmn, __shfl_down_sync(0xFFFFFFFFu, kmn, o));
    }
    if (lane == 0) { sred[w] = kmx; sred[4 + w] = kmn; }
    __syncthreads();
    kmx = fmaxf(fmaxf(sred[0], sred[1]), fmaxf(sred[2], sred[3]));
    kmn = fminf(fminf(sred[4], sred[5]), fminf(sred[6], sred[7]));

    const int n = blockIdx.x * 128 + t;
    const float qn = g_q[(size_t)bh * NPIX + n];
    // row max of q[n]*k2[m] (log2 domain); args of ex2 become <= 0
    const float nrm = -(qn >= 0.f ? qn * kmx : qn * kmn);

    float num0 = 0.f, num1 = 0.f, den0 = 0.f, den1 = 0.f;
    const float4* s4 = reinterpret_cast<const float4*>(s_kv);

    #pragma unroll 4
    for (int i = 0; i < NPIX / 2; i++) {
        float4 p = s4[i];                 // (k0,v0,k1,v1) — broadcast LDS.128
        float e0 = ex2f(fmaf(qn, p.x, nrm));
        float e1 = ex2f(fmaf(qn, p.z, nrm));
        num0 = fmaf(e0, p.y, num0);
        den0 += e0;
        num1 = fmaf(e1, p.w, num1);
        den1 += e1;
    }
    float num = num0 + num1;
    float den = den0 + den1;
    g_att[(size_t)bh * NPIX + n] = num / den;
}

// ---------------- Kernel C: output mix + residual + clip ----------------
__global__ void __launch_bounds__(256) out_kernel(
    const float* __restrict__ rgb,
    const float* __restrict__ wo,
    float* __restrict__ out)
{
    int idx = blockIdx.x * 256 + threadIdx.x;     // over B*NPIX pixels
    if (idx >= BATCH * NPIX) return;
    int b = idx >> 12;
    int n = idx & (NPIX - 1);

    float a0 = g_att[(b * CH + 0) * NPIX + n];
    float a1 = g_att[(b * CH + 1) * NPIX + n];
    float a2 = g_att[(b * CH + 2) * NPIX + n];

    #pragma unroll
    for (int c = 0; c < 3; c++) {
        float o = wo[3 * c] * a0 + wo[3 * c + 1] * a1 + wo[3 * c + 2] * a2;
        size_t off = ((size_t)b * CH + c) * NPIX + n;
        float val = rgb[off] + o;
        out[off] = fminf(fmaxf(val, 0.f), 1.f);
    }
}

extern "C" void kernel_launch(void* const* d_in, const int* in_sizes, int n_in,
                              void* d_out, int out_size)
{
    const float* rgb = (const float*)d_in[0];
    const float* wq  = (const float*)d_in[1];
    const float* wk  = (const float*)d_in[2];
    const float* wv  = (const float*)d_in[3];
    const float* wo  = (const float*)d_in[4];
    float* out = (float*)d_out;

    prep_kernel<<<BATCH, 1024>>>(rgb, wq, wk, wv);
    dim3 grid(NPIX / 128, NBH);
    attn_kernel<<<grid, 128>>>();
    out_kernel<<<(BATCH * NPIX + 255) / 256, 256>>>(rgb, wo, out);
}

// round 2
// speedup vs baseline: 3.0205x; 3.0205x over previous
#include <cuda_runtime.h>
#include <math.h>

// Problem constants (B=4, C=3=heads, c_h=1, H=W=64, N=4096, scale = 1)
#define BATCH 4
#define CH 3
#define NPIX 4096
#define NBH (BATCH * CH)
#define NBINS 256
#define LOG2E 1.4426950408889634f
#define LN2   0.6931471805599453f

// Scratch (device globals — no allocation allowed)
__device__ float  g_q[NBH * NPIX];              // gated q per (b,h,n)
__device__ float  g_mom[NBH * NBINS * 8];       // per-bin moments {S0,S1,S2,T0,T1,T2,0,0}
__device__ float2 g_stats[BATCH];               // (mu, inv_std) per batch
__device__ float4 g_kb[CH];                     // (kmin2, delta2, inv_delta2, center0) per channel

__device__ __forceinline__ float ex2f(float x) {
    float y;
    asm("ex2.approx.f32 %0, %1;" : "=f"(y) : "f"(x));
    return y;
}

// ---------------- Kernel A1: luma stats + bin setup + moment zeroing ----------------
__device__ __forceinline__ float block_sum_1024(float v) {
    __shared__ float sh[32];
    #pragma unroll
    for (int o = 16; o; o >>= 1) v += __shfl_down_sync(0xFFFFFFFFu, v, o);
    int lane = threadIdx.x & 31, w = threadIdx.x >> 5;
    if (lane == 0) sh[w] = v;
    __syncthreads();
    if (w == 0) {
        float r = sh[lane];
        #pragma unroll
        for (int o = 16; o; o >>= 1) r += __shfl_down_sync(0xFFFFFFFFu, r, o);
        if (lane == 0) sh[0] = r;
    }
    __syncthreads();
    float r = sh[0];
    __syncthreads();
    return r;
}

__global__ void __launch_bounds__(1024) stats_kernel(
    const float* __restrict__ rgb, const float* __restrict__ wk)
{
    const int b = blockIdx.x;
    const int t = threadIdx.x;

    // Zero the moment arrays (24576 floats over 4096 threads)
    int g = b * 1024 + t;
    #pragma unroll
    for (int i = 0; i < 6; i++) g_mom[g + i * 4096] = 0.f;

    const float* base = rgb + (size_t)b * CH * NPIX;
    float L[4];
    float sL = 0.f;
    #pragma unroll
    for (int i = 0; i < 4; i++) {
        int n = t + i * 1024;
        float rr = base[n];
        float gg = base[NPIX + n];
        float bb = base[2 * NPIX + n];
        L[i] = 0.299f * rr + 0.587f * gg + 0.114f * bb;
        sL += L[i];
    }
    float mu = block_sum_1024(sL) * (1.0f / NPIX);

    float s1 = 0.f, s2 = 0.f;
    #pragma unroll
    for (int i = 0; i < 4; i++) {
        float d = fabsf(L[i] - mu);
        s1 += d;
        s2 += d * d;
    }
    float S1 = block_sum_1024(s1);
    float S2 = block_sum_1024(s2);
    float var = (S2 - S1 * S1 * (1.0f / NPIX)) * (1.0f / (NPIX - 1));
    float stdv = sqrtf(fmaxf(var, 0.f)) + 1e-6f;

    if (t == 0) g_stats[b] = make_float2(mu, 1.0f / stdv);

    if (b == 0 && t == 0) {
        // Exact k-range bounds from weights: rgb in [0,1]
        #pragma unroll
        for (int c = 0; c < CH; c++) {
            float mn = 0.f, mx = 0.f;
            #pragma unroll
            for (int i = 0; i < 3; i++) {
                float w = wk[3 * c + i];
                mn += fminf(w, 0.f);
                mx += fmaxf(w, 0.f);
            }
            float kmin2 = mn * LOG2E, kmax2 = mx * LOG2E;
            float d = (kmax2 - kmin2) * (1.0f / NBINS);
            if (d < 1e-20f) d = 1e-20f;
            g_kb[c] = make_float4(kmin2, d, 1.0f / d, kmin2 + 0.5f * d);
        }
    }
}

// ---------------- Kernel A2: gate + 1x1 convs + moment binning ----------------
__global__ void __launch_bounds__(256) qkv_kernel(
    const float* __restrict__ rgb,
    const float* __restrict__ wq,
    const float* __restrict__ wk,
    const float* __restrict__ wv)
{
    const int bx = blockIdx.x;
    const int b = bx >> 4;
    const int t = threadIdx.x;
    const int n = ((bx & 15) << 8) + t;

    float2 st = g_stats[b];
    const float* base = rgb + (size_t)b * CH * NPIX;
    float rr = base[n];
    float gg = base[NPIX + n];
    float bb = base[2 * NPIX + n];
    float L = 0.299f * rr + 0.587f * gg + 0.114f * bb;
    float x = fabsf(L - st.x) * st.y;
    float gate = 1.0f / (1.0f + ex2f(-x * LOG2E));
    float gf = 1.0f + gate;

    #pragma unroll
    for (int c = 0; c < CH; c++) {
        float q = (wq[3 * c] * rr + wq[3 * c + 1] * gg + wq[3 * c + 2] * bb) * gf;
        float k = (wk[3 * c] * rr + wk[3 * c + 1] * gg + wk[3 * c + 2] * bb);
        float v = (wv[3 * c] * rr + wv[3 * c + 1] * gg + wv[3 * c + 2] * bb);
        int bh = b * CH + c;
        g_q[bh * NPIX + n] = q;

        float4 kb = g_kb[c];
        float k2 = k * LOG2E;
        int j = (int)((k2 - kb.x) * kb.z);
        j = max(0, min(NBINS - 1, j));
        float d2 = k2 - fmaf((float)j, kb.y, kb.w);   // k2 - center_j
        float* mp = g_mom + ((size_t)(bh * NBINS + j)) * 8;
        atomicAdd(mp + 0, v);
        atomicAdd(mp + 1, v * d2);
        atomicAdd(mp + 2, v * d2 * d2);
        atomicAdd(mp + 3, 1.0f);
        atomicAdd(mp + 4, d2);
        atomicAdd(mp + 5, d2 * d2);
    }
}

// ---------------- Kernel B: binned softmax-attention eval + output mix ----------------
// grid: (4 batches x 32 chunks) = 128 blocks, 384 threads (3 ch x 128 pixels)
__global__ void __launch_bounds__(384) attn_out_kernel(
    const float* __restrict__ rgb,
    const float* __restrict__ wo,
    float* __restrict__ out)
{
    __shared__ float4 s_mom[CH * NBINS * 2];   // 24 KB
    __shared__ float  s_att[384];

    const int bx = blockIdx.x;
    const int b = bx >> 5;
    const int chunk = bx & 31;
    const int t = threadIdx.x;

    const float4* gm4 = reinterpret_cast<const float4*>(g_mom);
    for (int i = t; i < CH * NBINS * 2; i += 384)
        s_mom[i] = gm4[b * CH * NBINS * 2 + i];
    __syncthreads();

    const int ch = t >> 7;          // warp-uniform (4 warps per channel)
    const int p = t & 127;
    const int n = (chunk << 7) + p;

    float q = g_q[(b * CH + ch) * NPIX + n];
    float4 kb = g_kb[ch];
    float u = q * LN2;
    float h = 0.5f * u * u;
    float step = q * kb.y;
    float c0 = q * kb.w;
    float cL = fmaf(255.f, step, c0);
    float arg = c0 - fmaxf(c0, cL);       // <= 0 always
    float step2 = step + step;

    float n0 = 0.f, n1 = 0.f, d0 = 0.f, d1 = 0.f;
    const float4* sp = s_mom + ch * NBINS * 2;

    #pragma unroll 4
    for (int j = 0; j < NBINS * 2; j += 4) {
        float4 A0 = sp[j],     B0 = sp[j + 1];
        float4 A1 = sp[j + 2], B1 = sp[j + 3];
        float e0 = ex2f(arg);
        float e1 = ex2f(arg + step);
        arg += step2;
        float pn0 = fmaf(h, A0.z, fmaf(u, A0.y, A0.x));
        float pd0 = fmaf(h, B0.y, fmaf(u, B0.x, A0.w));
        n0 = fmaf(e0, pn0, n0);
        d0 = fmaf(e0, pd0, d0);
        float pn1 = fmaf(h, A1.z, fmaf(u, A1.y, A1.x));
        float pd1 = fmaf(h, B1.y, fmaf(u, B1.x, A1.w));
        n1 = fmaf(e1, pn1, n1);
        d1 = fmaf(e1, pd1, d1);
    }
    s_att[t] = (n0 + n1) / (d0 + d1);
    __syncthreads();

    if (t < 128) {
        float a0 = s_att[t];
        float a1 = s_att[128 + t];
        float a2 = s_att[256 + t];
        int nn = (chunk << 7) + t;
        #pragma unroll
        for (int c = 0; c < CH; c++) {
            float o = wo[3 * c] * a0 + wo[3 * c + 1] * a1 + wo[3 * c + 2] * a2;
            size_t off = ((size_t)b * CH + c) * NPIX + nn;
            float val = rgb[off] + o;
            out[off] = fminf(fmaxf(val, 0.f), 1.f);
        }
    }
}

extern "C" void kernel_launch(void* const* d_in, const int* in_sizes, int n_in,
                              void* d_out, int out_size)
{
    const float* rgb = (const float*)d_in[0];
    const float* wq  = (const float*)d_in[1];
    const float* wk  = (const float*)d_in[2];
    const float* wv  = (const float*)d_in[3];
    const float* wo  = (const float*)d_in[4];
    float* out = (float*)d_out;

    stats_kernel<<<BATCH, 1024>>>(rgb, wk);
    qkv_kernel<<<BATCH * 16, 256>>>(rgb, wq, wk, wv);
    attn_out_kernel<<<BATCH * 32, 384>>>(rgb, wo, out);
}

// round 3
// speedup vs baseline: 3.2647x; 1.0808x over previous
#include <cuda_runtime.h>
#include <math.h>

// B=4, C=3=heads, c_h=1, H=W=64, N=4096, scale=1
#define BATCH 4
#define CH 3
#define NPIX 4096
#define NBH 12
#define NBINS 128
#define LOG2E 1.4426950408889634f
#define LN2   0.6931471805599453f
#define GRID  128
#define NTHR  384

// Ping-pong accumulators (zero-initialized for launch 0; each launch zeroes the alternate set)
__device__ float g_mom[2][NBH][NBINS][8];   // {S0,S1,S2,T0,T1,T2,pad,pad} per bin
__device__ float g_sums[2][BATCH][4];       // {sumL, s1, s2, pad} per batch
__device__ unsigned g_barcnt = 0;
__device__ unsigned g_bargen = 0;

__device__ __forceinline__ float ex2f(float x) {
    float y;
    asm("ex2.approx.f32 %0, %1;" : "=f"(y) : "f"(x));
    return y;
}

// Sense-style grid barrier. Safe: 128 blocks <= 148 SMs => all co-resident.
// gen is read BEFORE arriving, so the observed value is always the pre-bump one.
__device__ __forceinline__ void grid_barrier() {
    __syncthreads();
    if (threadIdx.x == 0) {
        unsigned gen = *(volatile unsigned*)&g_bargen;
        __threadfence();
        if (atomicAdd(&g_barcnt, 1) == GRID - 1) {
            g_barcnt = 0;
            __threadfence();
            atomicAdd(&g_bargen, 1);
        } else {
            while (*(volatile unsigned*)&g_bargen == gen) __nanosleep(20);
        }
        __threadfence();
    }
    __syncthreads();
}

__device__ __forceinline__ float warp_sum(float v) {
    #pragma unroll
    for (int o = 16; o; o >>= 1) v += __shfl_down_sync(0xFFFFFFFFu, v, o);
    return v;
}

__global__ void __launch_bounds__(NTHR) fused_kernel(
    const float* __restrict__ rgb,
    const float* __restrict__ wq,
    const float* __restrict__ wk,
    const float* __restrict__ wv,
    const float* __restrict__ wo,
    float* __restrict__ out)
{
    __shared__ float  s_rgb[CH][128];
    __shared__ float  s_scr[128];               // L, then dL
    __shared__ float4 s_mom[CH * NBINS * 2];    // 12 KB
    __shared__ float  s_att[NTHR];

    const int bx = blockIdx.x;
    const int b = bx >> 5;
    const int chunk = bx & 31;
    const int t = threadIdx.x;
    const int ch = t >> 7;          // warp-uniform
    const int p = t & 127;
    const int n = (chunk << 7) + p;

    // Launch parity from barrier generation (3 barriers per launch)
    const unsigned gen0 = *(volatile unsigned*)&g_bargen;
    const int pb = (int)((gen0 / 3u) & 1u);
    const int ab = pb ^ 1;

    // ---- Phase 1: load rgb, zero alternate buffers, batch luma sum ----
    float x = rgb[((size_t)b * CH + ch) * NPIX + n];
    s_rgb[ch][p] = x;

    {   // zero alt buffers (12288 floats / 128 blocks = 96 each)
        float* alt = &g_mom[ab][0][0][0];
        if (t < 96) alt[bx * 96 + t] = 0.f;
        if (bx == 0 && t < BATCH * 4) (&g_sums[ab][0][0])[t] = 0.f;
    }
    __syncthreads();

    if (t < 128) {
        float L = 0.299f * s_rgb[0][t] + 0.587f * s_rgb[1][t] + 0.114f * s_rgb[2][t];
        s_scr[t] = L;
        float s = warp_sum(L);
        if ((t & 31) == 0) atomicAdd(&g_sums[pb][b][0], s);
    }
    grid_barrier();   // ---- barrier 1 ----

    // ---- Phase 2: |L - mu| sums ----
    float mu = __ldcg(&g_sums[pb][b][0]) * (1.0f / NPIX);
    if (t < 128) {
        float d = fabsf(s_scr[t] - mu);
        s_scr[t] = d;
        float s1 = warp_sum(d);
        float s2 = warp_sum(d * d);
        if ((t & 31) == 0) {
            atomicAdd(&g_sums[pb][b][1], s1);
            atomicAdd(&g_sums[pb][b][2], s2);
        }
    }
    grid_barrier();   // ---- barrier 2 ----

    // ---- Phase 3: std, gate, qkv, moment binning ----
    float S1 = __ldcg(&g_sums[pb][b][1]);
    float S2 = __ldcg(&g_sums[pb][b][2]);
    float var = (S2 - S1 * S1 * (1.0f / NPIX)) * (1.0f / (NPIX - 1));
    float inv_std = 1.0f / (sqrtf(fmaxf(var, 0.f)) + 1e-6f);

    float dL = s_scr[p];
    float gate = 1.0f / (1.0f + ex2f(-dL * inv_std * LOG2E));
    float gf = 1.0f + gate;

    float rr = s_rgb[0][p], gg = s_rgb[1][p], bb = s_rgb[2][p];
    float q = (wq[3 * ch] * rr + wq[3 * ch + 1] * gg + wq[3 * ch + 2] * bb) * gf;
    float k = (wk[3 * ch] * rr + wk[3 * ch + 1] * gg + wk[3 * ch + 2] * bb);
    float v = (wv[3 * ch] * rr + wv[3 * ch + 1] * gg + wv[3 * ch + 2] * bb);

    // bin geometry from wk row (exact bounds: rgb in [0,1]) — all in registers
    float w0 = wk[3 * ch], w1 = wk[3 * ch + 1], w2 = wk[3 * ch + 2];
    float mn = fminf(w0, 0.f) + fminf(w1, 0.f) + fminf(w2, 0.f);
    float mx = fmaxf(w0, 0.f) + fmaxf(w1, 0.f) + fmaxf(w2, 0.f);
    float kmin2 = mn * LOG2E;
    float delta = (mx - mn) * (LOG2E / NBINS);
    if (delta < 1e-20f) delta = 1e-20f;
    float invd = 1.0f / delta;
    float cen0 = kmin2 + 0.5f * delta;

    float k2 = k * LOG2E;
    int j = (int)((k2 - kmin2) * invd);
    j = max(0, min(NBINS - 1, j));
    float d2 = k2 - fmaf((float)j, delta, cen0);
    float* mp = &g_mom[pb][b * CH + ch][j][0];
    atomicAdd(mp + 0, v);
    atomicAdd(mp + 1, v * d2);
    atomicAdd(mp + 2, v * d2 * d2);
    atomicAdd(mp + 3, 1.0f);
    atomicAdd(mp + 4, d2);
    atomicAdd(mp + 5, d2 * d2);

    grid_barrier();   // ---- barrier 3 ----

    // ---- Phase 4: load moments to SMEM, evaluate, output mix ----
    {
        const float4* gm4 = reinterpret_cast<const float4*>(&g_mom[pb][b * CH][0][0]);
        #pragma unroll
        for (int i = t; i < CH * NBINS * 2; i += NTHR) s_mom[i] = __ldcg(&gm4[i]);
    }
    __syncthreads();

    float u = q * LN2;
    float h = 0.5f * u * u;
    float step = q * delta;
    float c0 = q * cen0;
    float cL = fmaf((float)(NBINS - 1), step, c0);
    float arg = c0 - fmaxf(c0, cL);       // <= 0 always
    float step2 = step + step;

    float n0 = 0.f, n1 = 0.f, d0 = 0.f, d1 = 0.f;
    const float4* sp = s_mom + ch * NBINS * 2;

    #pragma unroll 4
    for (int jj = 0; jj < NBINS * 2; jj += 4) {
        float4 A0 = sp[jj],     B0 = sp[jj + 1];
        float4 A1 = sp[jj + 2], B1 = sp[jj + 3];
        float e0 = ex2f(arg);
        float e1 = ex2f(arg + step);
        arg += step2;
        float pn0 = fmaf(h, A0.z, fmaf(u, A0.y, A0.x));
        float pd0 = fmaf(h, B0.y, fmaf(u, B0.x, A0.w));
        n0 = fmaf(e0, pn0, n0);
        d0 = fmaf(e0, pd0, d0);
        float pn1 = fmaf(h, A1.z, fmaf(u, A1.y, A1.x));
        float pd1 = fmaf(h, B1.y, fmaf(u, B1.x, A1.w));
        n1 = fmaf(e1, pn1, n1);
        d1 = fmaf(e1, pd1, d1);
    }
    s_att[t] = (n0 + n1) / (d0 + d1);
    __syncthreads();

    if (t < 128) {
        float a0 = s_att[t];
        float a1 = s_att[128 + t];
        float a2 = s_att[256 + t];
        #pragma unroll
        for (int c = 0; c < 3; c++) {
            float o = wo[3 * c] * a0 + wo[3 * c + 1] * a1 + wo[3 * c + 2] * a2;
            size_t off = ((size_t)b * CH + c) * NPIX + n;
            float val = s_rgb[c][t] + o;
            out[off] = fminf(fmaxf(val, 0.f), 1.f);
        }
    }
}

extern "C" void kernel_launch(void* const* d_in, const int* in_sizes, int n_in,
                              void* d_out, int out_size)
{
    const float* rgb = (const float*)d_in[0];
    const float* wq  = (const float*)d_in[1];
    const float* wk  = (const float*)d_in[2];
    const float* wv  = (const float*)d_in[3];
    const float* wo  = (const float*)d_in[4];
    float* out = (float*)d_out;

    fused_kernel<<<GRID, NTHR>>>(rgb, wq, wk, wv, wo, out);
}

// round 4
// speedup vs baseline: 4.6804x; 1.4336x over previous
#include <cuda_runtime.h>
#include <math.h>

// B=4, C=3=heads, c_h=1, H=W=64, N=4096, scale=1
#define BATCH 4
#define CH 3
#define NPIX 4096
#define NBH 12
#define NBINS 128
#define LOG2E 1.4426950408889634f
#define LN2   0.6931471805599453f
#define GRID  128
#define NTHR  384
#define NWARP (NTHR / 32)

// Ping-pong moment accumulators: per bin {S0,S1,S2,T0} + {T1,T2,pad,pad}
__device__ float4 g_mom4[2][NBH][NBINS][2];
__device__ unsigned g_barcnt = 0;
__device__ unsigned g_bargen = 0;

__device__ __forceinline__ float ex2f(float x) {
    float y;
    asm("ex2.approx.f32 %0, %1;" : "=f"(y) : "f"(x));
    return y;
}

__device__ __forceinline__ void red_v4(float4* p, float a, float b, float c, float d) {
    asm volatile("red.global.add.v4.f32 [%0], {%1,%2,%3,%4};"
                 :: "l"(p), "f"(a), "f"(b), "f"(c), "f"(d) : "memory");
}
__device__ __forceinline__ void red_v2(float4* p, float a, float b) {
    asm volatile("red.global.add.v2.f32 [%0], {%1,%2};"
                 :: "l"(p), "f"(a), "f"(b) : "memory");
}

// Sense-style grid barrier (single use per launch). 128 blocks <= 148 SMs.
__device__ __forceinline__ void grid_barrier(unsigned gen) {
    __syncthreads();
    if (threadIdx.x == 0) {
        __threadfence();
        if (atomicAdd(&g_barcnt, 1) == GRID - 1) {
            g_barcnt = 0;
            __threadfence();
            atomicAdd(&g_bargen, 1);
        } else {
            while (*(volatile unsigned*)&g_bargen == gen) __nanosleep(20);
        }
        __threadfence();
    }
    __syncthreads();
}

__device__ __forceinline__ float warp_sum(float v) {
    #pragma unroll
    for (int o = 16; o; o >>= 1) v += __shfl_down_sync(0xFFFFFFFFu, v, o);
    return v;
}

__device__ __forceinline__ float block_sum(float v, float* sh) {
    v = warp_sum(v);
    int lane = threadIdx.x & 31, w = threadIdx.x >> 5;
    if (lane == 0) sh[w] = v;
    __syncthreads();
    float r;
    if (threadIdx.x == 0) {
        r = sh[0];
        #pragma unroll
        for (int i = 1; i < NWARP; i++) r += sh[i];
        sh[0] = r;
    }
    __syncthreads();
    r = sh[0];
    __syncthreads();
    return r;
}

__global__ void __launch_bounds__(NTHR) fused_kernel(
    const float* __restrict__ rgb,
    const float* __restrict__ wq,
    const float* __restrict__ wk,
    const float* __restrict__ wv,
    const float* __restrict__ wo,
    float* __restrict__ out)
{
    __shared__ float  s_L[NPIX];               // 16 KB: luma of whole batch
    __shared__ float  s_red[NWARP];
    __shared__ float4 s_mom[CH * NBINS * 2];   // 12 KB
    __shared__ float  s_att[NTHR];

    const int bx = blockIdx.x;
    const int b = bx >> 5;
    const int chunk = bx & 31;
    const int t = threadIdx.x;
    const int ch = t >> 7;          // warp-uniform
    const int p = t & 127;
    const int n = (chunk << 7) + p;

    const unsigned gen0 = *(volatile unsigned*)&g_bargen;
    const int pb = (int)(gen0 & 1u);
    const int ab = pb ^ 1;

    // ---- Phase A: redundant per-block batch stats ----
    const float* base = rgb + (size_t)b * CH * NPIX;
    float accL = 0.f;
    for (int i = t; i < NPIX; i += NTHR) {
        float L = 0.299f * base[i] + 0.587f * base[NPIX + i] + 0.114f * base[2 * NPIX + i];
        s_L[i] = L;
        accL += L;
    }
    // zero the alternate moment buffer for the next launch (24576 floats / 128 blocks)
    {
        float* alt = (float*)&g_mom4[ab][0][0][0];
        if (t < 192) alt[bx * 192 + t] = 0.f;
    }
    __syncthreads();
    float mu = block_sum(accL, s_red) * (1.0f / NPIX);

    float a1 = 0.f, a2 = 0.f;
    for (int i = t; i < NPIX; i += NTHR) {
        float d = fabsf(s_L[i] - mu);
        a1 += d;
        a2 += d * d;
    }
    float S1 = block_sum(a1, s_red);
    float S2 = block_sum(a2, s_red);
    float var = (S2 - S1 * S1 * (1.0f / NPIX)) * (1.0f / (NPIX - 1));
    float inv_std = 1.0f / (sqrtf(fmaxf(var, 0.f)) + 1e-6f);

    // ---- Phase B: own chunk gate + qkv + binned moment REDs ----
    float rr = base[n];
    float gg = base[NPIX + n];
    float bb = base[2 * NPIX + n];
    float dL = fabsf(s_L[n] - mu);
    float gate = 1.0f / (1.0f + ex2f(-dL * inv_std * LOG2E));
    float gf = 1.0f + gate;

    float q = (wq[3 * ch] * rr + wq[3 * ch + 1] * gg + wq[3 * ch + 2] * bb) * gf;
    float k = (wk[3 * ch] * rr + wk[3 * ch + 1] * gg + wk[3 * ch + 2] * bb);
    float v = (wv[3 * ch] * rr + wv[3 * ch + 1] * gg + wv[3 * ch + 2] * bb);

    // bin geometry from wk row (exact bounds: rgb in [0,1])
    float w0 = wk[3 * ch], w1 = wk[3 * ch + 1], w2 = wk[3 * ch + 2];
    float mn = fminf(w0, 0.f) + fminf(w1, 0.f) + fminf(w2, 0.f);
    float mx = fmaxf(w0, 0.f) + fmaxf(w1, 0.f) + fmaxf(w2, 0.f);
    float kmin2 = mn * LOG2E;
    float delta = (mx - mn) * (LOG2E / NBINS);
    if (delta < 1e-20f) delta = 1e-20f;
    float invd = 1.0f / delta;
    float cen0 = kmin2 + 0.5f * delta;

    float k2 = k * LOG2E;
    int j = (int)((k2 - kmin2) * invd);
    j = max(0, min(NBINS - 1, j));
    float d2 = k2 - fmaf((float)j, delta, cen0);
    float4* mp = &g_mom4[pb][b * CH + ch][j][0];
    red_v4(mp, v, v * d2, v * d2 * d2, 1.0f);
    red_v2(mp + 1, d2, d2 * d2);

    grid_barrier(gen0);   // ---- single grid barrier ----

    // ---- Phase C: load moments, evaluate, output mix ----
    {
        const float4* gm4 = &g_mom4[pb][b * CH][0][0];
        #pragma unroll
        for (int i = t; i < CH * NBINS * 2; i += NTHR) s_mom[i] = __ldcg(&gm4[i]);
    }
    __syncthreads();

    float u = q * LN2;
    float h = 0.5f * u * u;
    float step = q * delta;
    float c0 = q * cen0;
    float cL = fmaf((float)(NBINS - 1), step, c0);
    float arg = c0 - fmaxf(c0, cL);       // <= 0 always
    float step2 = step + step;

    float n0 = 0.f, n1 = 0.f, d0 = 0.f, d1 = 0.f;
    const float4* sp = s_mom + ch * NBINS * 2;

    #pragma unroll 4
    for (int jj = 0; jj < NBINS * 2; jj += 4) {
        float4 A0 = sp[jj],     B0 = sp[jj + 1];
        float4 A1 = sp[jj + 2], B1 = sp[jj + 3];
        float e0 = ex2f(arg);
        float e1 = ex2f(arg + step);
        arg += step2;
        float pn0 = fmaf(h, A0.z, fmaf(u, A0.y, A0.x));
        float pd0 = fmaf(h, B0.y, fmaf(u, B0.x, A0.w));
        n0 = fmaf(e0, pn0, n0);
        d0 = fmaf(e0, pd0, d0);
        float pn1 = fmaf(h, A1.z, fmaf(u, A1.y, A1.x));
        float pd1 = fmaf(h, B1.y, fmaf(u, B1.x, A1.w));
        n1 = fmaf(e1, pn1, n1);
        d1 = fmaf(e1, pd1, d1);
    }
    s_att[t] = (n0 + n1) / (d0 + d1);
    __syncthreads();

    if (t < 128) {
        float a0 = s_att[t];
        float a1o = s_att[128 + t];
        float a2o = s_att[256 + t];
        float px[3] = {rr, gg, bb};      // thread t<128 has ch=0, holds pixel n's rgb
        #pragma unroll
        for (int c = 0; c < 3; c++) {
            float o = wo[3 * c] * a0 + wo[3 * c + 1] * a1o + wo[3 * c + 2] * a2o;
            size_t off = ((size_t)b * CH + c) * NPIX + n;
            float val = px[c] + o;
            out[off] = fminf(fmaxf(val, 0.f), 1.f);
        }
    }
}

extern "C" void kernel_launch(void* const* d_in, const int* in_sizes, int n_in,
                              void* d_out, int out_size)
{
    const float* rgb = (const float*)d_in[0];
    const float* wq  = (const float*)d_in[1];
    const float* wk  = (const float*)d_in[2];
    const float* wv  = (const float*)d_in[3];
    const float* wo  = (const float*)d_in[4];
    float* out = (float*)d_out;

    fused_kernel<<<GRID, NTHR>>>(rgb, wq, wk, wv, wo, out);
}

// round 5
// speedup vs baseline: 5.2276x; 1.1169x over previous
#include <cuda_runtime.h>
#include <math.h>

// B=4, C=3=heads, c_h=1, H=W=64, N=4096, scale=1
#define BATCH 4
#define CH 3
#define NPIX 4096
#define NBH 12
#define NBINS 64
#define HBINS (NBINS / 2)
#define LOG2E 1.4426950408889634f
#define LN2   0.6931471805599453f
#define GRID  128
#define BPB   32          // blocks per batch
#define NTHR  768
#define NWARP (NTHR / 32)

// Ping-pong moment accumulators: per bin {S0,S1,S2,T0} + {T1,T2,pad,pad}
__device__ float4 g_mom4[2][NBH][NBINS][2];
__device__ unsigned g_cnt[BATCH] = {0, 0, 0, 0};
__device__ unsigned g_gen[BATCH] = {0, 0, 0, 0};

__device__ __forceinline__ float ex2f(float x) {
    float y;
    asm("ex2.approx.f32 %0, %1;" : "=f"(y) : "f"(x));
    return y;
}

__device__ __forceinline__ void red_v4(float4* p, float a, float b, float c, float d) {
    asm volatile("red.global.add.v4.f32 [%0], {%1,%2,%3,%4};"
                 :: "l"(p), "f"(a), "f"(b), "f"(c), "f"(d) : "memory");
}
__device__ __forceinline__ void red_v2(float4* p, float a, float b) {
    asm volatile("red.global.add.v2.f32 [%0], {%1,%2};"
                 :: "l"(p), "f"(a), "f"(b) : "memory");
}

__device__ __forceinline__ float warp_sum(float v) {
    #pragma unroll
    for (int o = 16; o; o >>= 1) v += __shfl_down_sync(0xFFFFFFFFu, v, o);
    return v;
}

__device__ __forceinline__ float block_sum(float v, float* sh) {
    v = warp_sum(v);
    int lane = threadIdx.x & 31, w = threadIdx.x >> 5;
    if (lane == 0) sh[w] = v;
    __syncthreads();
    float r;
    if (threadIdx.x == 0) {
        r = sh[0];
        #pragma unroll
        for (int i = 1; i < NWARP; i++) r += sh[i];
        sh[0] = r;
    }
    __syncthreads();
    r = sh[0];
    __syncthreads();
    return r;
}

__global__ void __launch_bounds__(NTHR) fused_kernel(
    const float* __restrict__ rgb,
    const float* __restrict__ wq,
    const float* __restrict__ wk,
    const float* __restrict__ wv,
    const float* __restrict__ wo,
    float* __restrict__ out)
{
    __shared__ float  s_L[NPIX];               // 16 KB
    __shared__ float  s_red[NWARP];
    __shared__ float4 s_mom[CH * NBINS * 2];   // 6 KB
    __shared__ float2 s_nd[NTHR];              // 6 KB partial num/den
    __shared__ float  s_att[384];

    const int bx = blockIdx.x;
    const int b = bx >> 5;
    const int chunk = bx & 31;
    const int t = threadIdx.x;
    const int half = (t >= 384) ? 1 : 0;       // bin-half this thread sums
    const int task = t - half * 384;           // 0..383
    const int ch = task >> 7;                  // warp-uniform
    const int p = task & 127;
    const int n = (chunk << 7) + p;

    const unsigned gen0 = *(volatile unsigned*)&g_gen[b];
    const int pb = (int)(gen0 & 1u);
    const int ab = pb ^ 1;

    // ---- Phase A: redundant per-block batch stats ----
    const float* base = rgb + (size_t)b * CH * NPIX;
    float accL = 0.f;
    for (int i = t; i < NPIX; i += NTHR) {
        float L = 0.299f * base[i] + 0.587f * base[NPIX + i] + 0.114f * base[2 * NPIX + i];
        s_L[i] = L;
        accL += L;
    }
    {   // zero alternate moment buffer (6144 floats / 128 blocks = 48 each)
        float* alt = (float*)&g_mom4[ab][0][0][0];
        if (t < 48) alt[bx * 48 + t] = 0.f;
    }
    __syncthreads();
    float mu = block_sum(accL, s_red) * (1.0f / NPIX);

    float a1 = 0.f, a2 = 0.f;
    for (int i = t; i < NPIX; i += NTHR) {
        float d = fabsf(s_L[i] - mu);
        a1 += d;
        a2 += d * d;
    }
    float S1 = block_sum(a1, s_red);
    float S2 = block_sum(a2, s_red);
    float var = (S2 - S1 * S1 * (1.0f / NPIX)) * (1.0f / (NPIX - 1));
    float inv_std = 1.0f / (sqrtf(fmaxf(var, 0.f)) + 1e-6f);

    // ---- Phase B: gate + qkv (both halves compute q identically; only half 0 REDs) ----
    float rr = base[n];
    float gg = base[NPIX + n];
    float bb = base[2 * NPIX + n];
    float dL = fabsf(s_L[n] - mu);
    float gate = 1.0f / (1.0f + ex2f(-dL * inv_std * LOG2E));
    float gf = 1.0f + gate;

    float q = (wq[3 * ch] * rr + wq[3 * ch + 1] * gg + wq[3 * ch + 2] * bb) * gf;

    // bin geometry from wk row (exact bounds: rgb in [0,1])
    float w0 = wk[3 * ch], w1 = wk[3 * ch + 1], w2 = wk[3 * ch + 2];
    float mn = fminf(w0, 0.f) + fminf(w1, 0.f) + fminf(w2, 0.f);
    float mx = fmaxf(w0, 0.f) + fmaxf(w1, 0.f) + fmaxf(w2, 0.f);
    float kmin2 = mn * LOG2E;
    float delta = (mx - mn) * (LOG2E / NBINS);
    if (delta < 1e-20f) delta = 1e-20f;
    float cen0 = kmin2 + 0.5f * delta;

    if (half == 0) {
        float k = (wk[3 * ch] * rr + wk[3 * ch + 1] * gg + wk[3 * ch + 2] * bb);
        float v = (wv[3 * ch] * rr + wv[3 * ch + 1] * gg + wv[3 * ch + 2] * bb);
        float k2 = k * LOG2E;
        int j = (int)((k2 - kmin2) * (1.0f / delta));
        j = max(0, min(NBINS - 1, j));
        float d2 = k2 - fmaf((float)j, delta, cen0);
        float4* mp = &g_mom4[pb][b * CH + ch][j][0];
        red_v4(mp, v, v * d2, v * d2 * d2, 1.0f);
        red_v2(mp + 1, d2, d2 * d2);
    }

    // ---- per-batch grid barrier (32 blocks) ----
    __syncthreads();
    if (t == 0) {
        __threadfence();
        if (atomicAdd(&g_cnt[b], 1) == BPB - 1) {
            g_cnt[b] = 0;
            __threadfence();
            atomicAdd(&g_gen[b], 1);
        } else {
            while (*(volatile unsigned*)&g_gen[b] == gen0) __nanosleep(20);
        }
        __threadfence();
    }
    __syncthreads();

    // ---- Phase C: load moments, evaluate (split bins), combine, output ----
    {
        const float4* gm4 = &g_mom4[pb][b * CH][0][0];
        #pragma unroll
        for (int i = t; i < CH * NBINS * 2; i += NTHR) s_mom[i] = __ldcg(&gm4[i]);
    }
    __syncthreads();

    float u = q * LN2;
    float h2 = 0.5f * u * u;
    float step = q * delta;
    float c0 = q * cen0;
    float cL = fmaf((float)(NBINS - 1), step, c0);
    float offs = -fmaxf(c0, cL);                        // global row max over all bins
    float arg = fmaf((float)(half * HBINS), step, c0) + offs;
    float step2 = step + step;

    float n0 = 0.f, n1 = 0.f, d0 = 0.f, d1 = 0.f;
    const float4* sp = s_mom + (ch * NBINS + half * HBINS) * 2;

    #pragma unroll 8
    for (int jj = 0; jj < HBINS * 2; jj += 4) {
        float4 A0 = sp[jj],     B0 = sp[jj + 1];
        float4 A1 = sp[jj + 2], B1 = sp[jj + 3];
        float e0 = ex2f(arg);
        float e1 = ex2f(arg + step);
        arg += step2;
        float pn0 = fmaf(h2, A0.z, fmaf(u, A0.y, A0.x));
        float pd0 = fmaf(h2, B0.y, fmaf(u, B0.x, A0.w));
        n0 = fmaf(e0, pn0, n0);
        d0 = fmaf(e0, pd0, d0);
        float pn1 = fmaf(h2, A1.z, fmaf(u, A1.y, A1.x));
        float pd1 = fmaf(h2, B1.y, fmaf(u, B1.x, A1.w));
        n1 = fmaf(e1, pn1, n1);
        d1 = fmaf(e1, pd1, d1);
    }
    s_nd[t] = make_float2(n0 + n1, d0 + d1);
    __syncthreads();

    if (half == 0) {
        float2 lo = s_nd[t], hi = s_nd[t + 384];
        s_att[t] = (lo.x + hi.x) / (lo.y + hi.y);
    }
    __syncthreads();

    if (t < 128) {
        float a0 = s_att[t];
        float a1o = s_att[128 + t];
        float a2o = s_att[256 + t];
        float px[3] = {rr, gg, bb};      // t<128 => ch=0, half=0, pixel n
        #pragma unroll
        for (int c = 0; c < 3; c++) {
            float o = wo[3 * c] * a0 + wo[3 * c + 1] * a1o + wo[3 * c + 2] * a2o;
            size_t off = ((size_t)b * CH + c) * NPIX + n;
            float val = px[c] + o;
            out[off] = fminf(fmaxf(val, 0.f), 1.f);
        }
    }
}

extern "C" void kernel_launch(void* const* d_in, const int* in_sizes, int n_in,
                              void* d_out, int out_size)
{
    const float* rgb = (const float*)d_in[0];
    const float* wq  = (const float*)d_in[1];
    const float* wk  = (const float*)d_in[2];
    const float* wv  = (const float*)d_in[3];
    const float* wo  = (const float*)d_in[4];
    float* out = (float*)d_out;

    fused_kernel<<<GRID, NTHR>>>(rgb, wq, wk, wv, wo, out);
}

// round 6
// speedup vs baseline: 5.6524x; 1.0813x over previous
#include <cuda_runtime.h>
#include <math.h>

// B=4, C=3=heads, c_h=1, H=W=64, N=4096, scale=1
#define BATCH 4
#define CH 3
#define NPIX 4096
#define NBH 12
#define NBINS 32
#define HBINS (NBINS / 2)
#define LOG2E 1.4426950408889634f
#define LN2   0.6931471805599453f
#define GRID  128
#define BPB   32          // blocks per batch
#define NTHR  768
#define NWARP (NTHR / 32)

// Ping-pong moment accumulators: per bin {S0,S1,S2,T0} + {T1,T2,pad,pad}
__device__ float4 g_mom4[2][NBH][NBINS][2];
__device__ unsigned g_cnt[BATCH] = {0, 0, 0, 0};
__device__ unsigned g_gen[BATCH] = {0, 0, 0, 0};

__device__ __forceinline__ float ex2f(float x) {
    float y;
    asm("ex2.approx.f32 %0, %1;" : "=f"(y) : "f"(x));
    return y;
}

__device__ __forceinline__ void red_v4(float4* p, float a, float b, float c, float d) {
    asm volatile("red.global.add.v4.f32 [%0], {%1,%2,%3,%4};"
                 :: "l"(p), "f"(a), "f"(b), "f"(c), "f"(d) : "memory");
}
__device__ __forceinline__ void red_v2(float4* p, float a, float b) {
    asm volatile("red.global.add.v2.f32 [%0], {%1,%2};"
                 :: "l"(p), "f"(a), "f"(b) : "memory");
}
__device__ __forceinline__ unsigned atom_add_acqrel(unsigned* p, unsigned v) {
    unsigned old;
    asm volatile("atom.acq_rel.gpu.global.add.u32 %0, [%1], %2;"
                 : "=r"(old) : "l"(p), "r"(v) : "memory");
    return old;
}
__device__ __forceinline__ void red_add_release(unsigned* p, unsigned v) {
    asm volatile("red.release.gpu.global.add.u32 [%0], %1;"
                 :: "l"(p), "r"(v) : "memory");
}
__device__ __forceinline__ unsigned ld_acquire(const unsigned* p) {
    unsigned v;
    asm volatile("ld.acquire.gpu.global.u32 %0, [%1];" : "=r"(v) : "l"(p) : "memory");
    return v;
}

__device__ __forceinline__ float warp_sum(float v) {
    #pragma unroll
    for (int o = 16; o; o >>= 1) v += __shfl_down_sync(0xFFFFFFFFu, v, o);
    return v;
}

// Two-stage block sum (24 warps -> warp0 reduce), dedicated broadcast slot.
__device__ __forceinline__ float block_sum(float v, float* sh, float* bcast) {
    v = warp_sum(v);
    int lane = threadIdx.x & 31, w = threadIdx.x >> 5;
    if (lane == 0) sh[w] = v;
    __syncthreads();
    if (w == 0) {
        float r = (lane < NWARP) ? sh[lane] : 0.f;
        r = warp_sum(r);
        if (lane == 0) *bcast = r;
    }
    __syncthreads();
    return *bcast;
}

__device__ __forceinline__ float2 block_sum2(float a, float b, float2* sh, float2* bcast) {
    a = warp_sum(a);
    b = warp_sum(b);
    int lane = threadIdx.x & 31, w = threadIdx.x >> 5;
    if (lane == 0) sh[w] = make_float2(a, b);
    __syncthreads();
    if (w == 0) {
        float2 rv = (lane < NWARP) ? sh[lane] : make_float2(0.f, 0.f);
        rv.x = warp_sum(rv.x);
        rv.y = warp_sum(rv.y);
        if (lane == 0) *bcast = rv;
    }
    __syncthreads();
    return *bcast;
}

__global__ void __launch_bounds__(NTHR) fused_kernel(
    const float* __restrict__ rgb,
    const float* __restrict__ wq,
    const float* __restrict__ wk,
    const float* __restrict__ wv,
    const float* __restrict__ wo,
    float* __restrict__ out)
{
    __shared__ float  s_L[NPIX];               // 16 KB
    __shared__ float  s_red[NWARP];
    __shared__ float2 s_red2[NWARP];
    __shared__ float  s_bc1;
    __shared__ float2 s_bc2;
    __shared__ float4 s_mom[CH * NBINS * 2];   // 3 KB
    __shared__ float2 s_nd[NTHR];              // 6 KB
    __shared__ float  s_att[384];

    const int bx = blockIdx.x;
    const int b = bx >> 5;
    const int chunk = bx & 31;
    const int t = threadIdx.x;
    const int half = (t >= 384) ? 1 : 0;
    const int task = t - half * 384;           // 0..383
    const int ch = task >> 7;                  // warp-uniform
    const int p = task & 127;
    const int n = (chunk << 7) + p;

    const unsigned gen0 = ld_acquire(&g_gen[b]);
    const int pb = (int)(gen0 & 1u);
    const int ab = pb ^ 1;

    // ---- Phase A: vectorized batch luma, L kept in registers ----
    const float* base = rgb + (size_t)b * CH * NPIX;
    const float4* b4 = (const float4*)base;    // planes: r[0,1024) g[1024,2048) b[2048,3072)
    float4 La, Lb = make_float4(0.f, 0.f, 0.f, 0.f);
    float accL;
    {
        float4 r4 = b4[t], g4 = b4[1024 + t], v4 = b4[2048 + t];
        La.x = 0.299f * r4.x + 0.587f * g4.x + 0.114f * v4.x;
        La.y = 0.299f * r4.y + 0.587f * g4.y + 0.114f * v4.y;
        La.z = 0.299f * r4.z + 0.587f * g4.z + 0.114f * v4.z;
        La.w = 0.299f * r4.w + 0.587f * g4.w + 0.114f * v4.w;
        ((float4*)s_L)[t] = La;
        accL = (La.x + La.y) + (La.z + La.w);
    }
    if (t < 256) {
        int i = t + 768;
        float4 r4 = b4[i], g4 = b4[1024 + i], v4 = b4[2048 + i];
        Lb.x = 0.299f * r4.x + 0.587f * g4.x + 0.114f * v4.x;
        Lb.y = 0.299f * r4.y + 0.587f * g4.y + 0.114f * v4.y;
        Lb.z = 0.299f * r4.z + 0.587f * g4.z + 0.114f * v4.z;
        Lb.w = 0.299f * r4.w + 0.587f * g4.w + 0.114f * v4.w;
        ((float4*)s_L)[i] = Lb;
        accL += (Lb.x + Lb.y) + (Lb.z + Lb.w);
    }
    {   // zero alternate moment buffer (3072 floats / 128 blocks = 24 each)
        float* alt = (float*)&g_mom4[ab][0][0][0];
        if (t < 24) alt[bx * 24 + t] = 0.f;
    }
    float mu = block_sum(accL, s_red, &s_bc1) * (1.0f / NPIX);

    // ---- |L - mu| sums from registers ----
    float a1, a2;
    {
        float d0 = fabsf(La.x - mu), d1 = fabsf(La.y - mu);
        float d2 = fabsf(La.z - mu), d3 = fabsf(La.w - mu);
        a1 = (d0 + d1) + (d2 + d3);
        a2 = fmaf(d0, d0, fmaf(d1, d1, fmaf(d2, d2, d3 * d3)));
    }
    if (t < 256) {
        float d0 = fabsf(Lb.x - mu), d1 = fabsf(Lb.y - mu);
        float d2 = fabsf(Lb.z - mu), d3 = fabsf(Lb.w - mu);
        a1 += (d0 + d1) + (d2 + d3);
        a2 += fmaf(d0, d0, fmaf(d1, d1, fmaf(d2, d2, d3 * d3)));
    }
    float2 S = block_sum2(a1, a2, s_red2, &s_bc2);
    float var = (S.y - S.x * S.x * (1.0f / NPIX)) * (1.0f / (NPIX - 1));
    float inv_std = 1.0f / (sqrtf(fmaxf(var, 0.f)) + 1e-6f);

    // ---- Phase B: gate + q (all); k,v + REDs (half 0 only) ----
    float rr = base[n];
    float gg = base[NPIX + n];
    float bb = base[2 * NPIX + n];
    float dL = fabsf(s_L[n] - mu);
    float gate = 1.0f / (1.0f + ex2f(-dL * inv_std * LOG2E));
    float gf = 1.0f + gate;

    float q = (wq[3 * ch] * rr + wq[3 * ch + 1] * gg + wq[3 * ch + 2] * bb) * gf;

    // bin geometry from wk row (exact bounds: rgb in [0,1])
    float w0 = wk[3 * ch], w1 = wk[3 * ch + 1], w2 = wk[3 * ch + 2];
    float mn = fminf(w0, 0.f) + fminf(w1, 0.f) + fminf(w2, 0.f);
    float mx = fmaxf(w0, 0.f) + fmaxf(w1, 0.f) + fmaxf(w2, 0.f);
    float kmin2 = mn * LOG2E;
    float delta = (mx - mn) * (LOG2E / NBINS);
    if (delta < 1e-20f) delta = 1e-20f;
    float cen0 = kmin2 + 0.5f * delta;

    if (half == 0) {
        float k = (w0 * rr + w1 * gg + w2 * bb);
        float v = (wv[3 * ch] * rr + wv[3 * ch + 1] * gg + wv[3 * ch + 2] * bb);
        float k2 = k * LOG2E;
        int j = (int)((k2 - kmin2) * (1.0f / delta));
        j = max(0, min(NBINS - 1, j));
        float d2 = k2 - fmaf((float)j, delta, cen0);
        float4* mp = &g_mom4[pb][b * CH + ch][j][0];
        red_v4(mp, v, v * d2, v * d2 * d2, 1.0f);
        red_v2(mp + 1, d2, d2 * d2);
    }

    // ---- per-batch grid barrier (32 blocks), acq/rel scoped ----
    __syncthreads();
    if (t == 0) {
        if (atom_add_acqrel(&g_cnt[b], 1) == BPB - 1) {
            asm volatile("st.relaxed.gpu.global.u32 [%0], %1;" :: "l"(&g_cnt[b]), "r"(0u) : "memory");
            red_add_release(&g_gen[b], 1);
        } else {
            while (ld_acquire(&g_gen[b]) == gen0) { }
        }
    }
    __syncthreads();

    // ---- Phase C: load moments, evaluate (split bins), combine, output ----
    {
        const float4* gm4 = &g_mom4[pb][b * CH][0][0];
        if (t < CH * NBINS * 2) s_mom[t] = __ldcg(&gm4[t]);
    }
    __syncthreads();

    float u = q * LN2;
    float h2 = 0.5f * u * u;
    float step = q * delta;
    float c0 = q * cen0;
    float cL = fmaf((float)(NBINS - 1), step, c0);
    float offs = -fmaxf(c0, cL);                        // global row max
    float arg = fmaf((float)(half * HBINS), step, c0) + offs;
    float step2 = step + step;

    float n0 = 0.f, n1 = 0.f, d0a = 0.f, d1a = 0.f;
    const float4* sp = s_mom + (ch * NBINS + half * HBINS) * 2;

    #pragma unroll 8
    for (int jj = 0; jj < HBINS * 2; jj += 4) {
        float4 A0 = sp[jj],     B0 = sp[jj + 1];
        float4 A1 = sp[jj + 2], B1 = sp[jj + 3];
        float e0 = ex2f(arg);
        float e1 = ex2f(arg + step);
        arg += step2;
        float pn0 = fmaf(h2, A0.z, fmaf(u, A0.y, A0.x));
        float pd0 = fmaf(h2, B0.y, fmaf(u, B0.x, A0.w));
        n0 = fmaf(e0, pn0, n0);
        d0a = fmaf(e0, pd0, d0a);
        float pn1 = fmaf(h2, A1.z, fmaf(u, A1.y, A1.x));
        float pd1 = fmaf(h2, B1.y, fmaf(u, B1.x, A1.w));
        n1 = fmaf(e1, pn1, n1);
        d1a = fmaf(e1, pd1, d1a);
    }
    s_nd[t] = make_float2(n0 + n1, d0a + d1a);
    __syncthreads();

    if (half == 0) {
        float2 lo = s_nd[t], hi = s_nd[t + 384];
        s_att[t] = (lo.x + hi.x) / (lo.y + hi.y);
    }
    __syncthreads();

    if (t < 128) {
        float a0 = s_att[t];
        float a1o = s_att[128 + t];
        float a2o = s_att[256 + t];
        float px[3] = {rr, gg, bb};      // t<128 => ch=0, half=0, pixel n
        #pragma unroll
        for (int c = 0; c < 3; c++) {
            float o = wo[3 * c] * a0 + wo[3 * c + 1] * a1o + wo[3 * c + 2] * a2o;
            size_t off = ((size_t)b * CH + c) * NPIX + n;
            float val = px[c] + o;
            out[off] = fminf(fmaxf(val, 0.f), 1.f);
        }
    }
}

extern "C" void kernel_launch(void* const* d_in, const int* in_sizes, int n_in,
                              void* d_out, int out_size)
{
    const float* rgb = (const float*)d_in[0];
    const float* wq  = (const float*)d_in[1];
    const float* wk  = (const float*)d_in[2];
    const float* wv  = (const float*)d_in[3];
    const float* wo  = (const float*)d_in[4];
    float* out = (float*)d_out;

    fused_kernel<<<GRID, NTHR>>>(rgb, wq, wk, wv, wo, out);
}

// round 7
// speedup vs baseline: 6.3392x; 1.1215x over previous
#include <cuda_runtime.h>
#include <math.h>

// B=4, C=3=heads, c_h=1, H=W=64, N=4096, scale=1
#define BATCH 4
#define CH 3
#define NPIX 4096
#define NBH 12
#define NBINS 32
#define HBINS (NBINS / 2)
#define LOG2E 1.4426950408889634f
#define LN2   0.6931471805599453f
#define GRID  128
#define BPB   32          // blocks per batch
#define NTHR  768
#define NWARP (NTHR / 32)

// Ping-pong moment accumulators: per bin {S0,S1,S2,T0} + {T1,T2,pad,pad}
__device__ float4 g_mom4[2][NBH][NBINS][2];
__device__ unsigned g_cnt[BATCH] = {0, 0, 0, 0};
__device__ unsigned g_gen[BATCH] = {0, 0, 0, 0};

__device__ __forceinline__ float ex2f(float x) {
    float y;
    asm("ex2.approx.f32 %0, %1;" : "=f"(y) : "f"(x));
    return y;
}

__device__ __forceinline__ void red_v4(float4* p, float a, float b, float c, float d) {
    asm volatile("red.global.add.v4.f32 [%0], {%1,%2,%3,%4};"
                 :: "l"(p), "f"(a), "f"(b), "f"(c), "f"(d) : "memory");
}
__device__ __forceinline__ void red_v2(float4* p, float a, float b) {
    asm volatile("red.global.add.v2.f32 [%0], {%1,%2};"
                 :: "l"(p), "f"(a), "f"(b) : "memory");
}
__device__ __forceinline__ unsigned atom_add_acqrel(unsigned* p, unsigned v) {
    unsigned old;
    asm volatile("atom.acq_rel.gpu.global.add.u32 %0, [%1], %2;"
                 : "=r"(old) : "l"(p), "r"(v) : "memory");
    return old;
}
__device__ __forceinline__ void red_add_release(unsigned* p, unsigned v) {
    asm volatile("red.release.gpu.global.add.u32 [%0], %1;"
                 :: "l"(p), "r"(v) : "memory");
}
__device__ __forceinline__ unsigned ld_acquire(const unsigned* p) {
    unsigned v;
    asm volatile("ld.acquire.gpu.global.u32 %0, [%1];" : "=r"(v) : "l"(p) : "memory");
    return v;
}

__device__ __forceinline__ float warp_sum(float v) {
    #pragma unroll
    for (int o = 16; o; o >>= 1) v += __shfl_down_sync(0xFFFFFFFFu, v, o);
    return v;
}

__device__ __forceinline__ float block_sum(float v, float* sh, float* bcast) {
    v = warp_sum(v);
    int lane = threadIdx.x & 31, w = threadIdx.x >> 5;
    if (lane == 0) sh[w] = v;
    __syncthreads();
    if (w == 0) {
        float r = (lane < NWARP) ? sh[lane] : 0.f;
        r = warp_sum(r);
        if (lane == 0) *bcast = r;
    }
    __syncthreads();
    return *bcast;
}

__device__ __forceinline__ float2 block_sum2(float a, float b, float2* sh, float2* bcast) {
    a = warp_sum(a);
    b = warp_sum(b);
    int lane = threadIdx.x & 31, w = threadIdx.x >> 5;
    if (lane == 0) sh[w] = make_float2(a, b);
    __syncthreads();
    if (w == 0) {
        float2 rv = (lane < NWARP) ? sh[lane] : make_float2(0.f, 0.f);
        rv.x = warp_sum(rv.x);
        rv.y = warp_sum(rv.y);
        if (lane == 0) *bcast = rv;
    }
    __syncthreads();
    return *bcast;
}

__global__ void __launch_bounds__(NTHR) fused_kernel(
    const float* __restrict__ rgb,
    const float* __restrict__ wq,
    const float* __restrict__ wk,
    const float* __restrict__ wv,
    const float* __restrict__ wo,
    float* __restrict__ out)
{
    __shared__ float  s_red[NWARP];
    __shared__ float2 s_red2[NWARP];
    __shared__ float  s_bc1;
    __shared__ float2 s_bc2;
    __shared__ float4 s_mom[CH * NBINS * 2];   // 3 KB
    __shared__ float2 s_nd[NTHR];              // 6 KB

    const int bx = blockIdx.x;
    const int b = bx >> 5;
    const int chunk = bx & 31;
    const int t = threadIdx.x;
    const int half = (t >= 384) ? 1 : 0;
    const int task = t - half * 384;           // 0..383
    const int ch = task >> 7;                  // warp-uniform
    const int p = task & 127;
    const int n = (chunk << 7) + p;

    const unsigned gen0 = ld_acquire(&g_gen[b]);
    const int pb = (int)(gen0 & 1u);
    const int ab = pb ^ 1;

    // ---- Prefetch: own pixel + weight rows (overlaps with luma loop) ----
    const float* base = rgb + (size_t)b * CH * NPIX;
    float rr = base[n];
    float gg = base[NPIX + n];
    float bb = base[2 * NPIX + n];
    float wq0 = wq[3 * ch], wq1 = wq[3 * ch + 1], wq2 = wq[3 * ch + 2];
    float w0  = wk[3 * ch], w1  = wk[3 * ch + 1], w2  = wk[3 * ch + 2];
    float wv0 = wv[3 * ch], wv1 = wv[3 * ch + 1], wv2 = wv[3 * ch + 2];

    // ---- Phase A: vectorized batch luma, all in registers ----
    const float4* b4 = (const float4*)base;    // planes: r[0,1024) g[1024,2048) b[2048,3072)
    float4 La, Lb = make_float4(0.f, 0.f, 0.f, 0.f);
    float accL;
    {
        float4 r4 = b4[t], g4 = b4[1024 + t], v4 = b4[2048 + t];
        La.x = 0.299f * r4.x + 0.587f * g4.x + 0.114f * v4.x;
        La.y = 0.299f * r4.y + 0.587f * g4.y + 0.114f * v4.y;
        La.z = 0.299f * r4.z + 0.587f * g4.z + 0.114f * v4.z;
        La.w = 0.299f * r4.w + 0.587f * g4.w + 0.114f * v4.w;
        accL = (La.x + La.y) + (La.z + La.w);
    }
    if (t >= 512) {                            // extras on half=1 threads (they skip REDs)
        int i = t + 256;                       // 768..1023
        float4 r4 = b4[i], g4 = b4[1024 + i], v4 = b4[2048 + i];
        Lb.x = 0.299f * r4.x + 0.587f * g4.x + 0.114f * v4.x;
        Lb.y = 0.299f * r4.y + 0.587f * g4.y + 0.114f * v4.y;
        Lb.z = 0.299f * r4.z + 0.587f * g4.z + 0.114f * v4.z;
        Lb.w = 0.299f * r4.w + 0.587f * g4.w + 0.114f * v4.w;
        accL += (Lb.x + Lb.y) + (Lb.z + Lb.w);
    }
    {   // zero alternate moment buffer (3072 floats / 128 blocks = 24 each)
        float* alt = (float*)&g_mom4[ab][0][0][0];
        if (t < 24) alt[bx * 24 + t] = 0.f;
    }
    float mu = block_sum(accL, s_red, &s_bc1) * (1.0f / NPIX);

    // ---- |L - mu| sums from registers ----
    float a1, a2;
    {
        float d0 = fabsf(La.x - mu), d1 = fabsf(La.y - mu);
        float d2 = fabsf(La.z - mu), d3 = fabsf(La.w - mu);
        a1 = (d0 + d1) + (d2 + d3);
        a2 = fmaf(d0, d0, fmaf(d1, d1, fmaf(d2, d2, d3 * d3)));
    }
    if (t >= 512) {
        float d0 = fabsf(Lb.x - mu), d1 = fabsf(Lb.y - mu);
        float d2 = fabsf(Lb.z - mu), d3 = fabsf(Lb.w - mu);
        a1 += (d0 + d1) + (d2 + d3);
        a2 += fmaf(d0, d0, fmaf(d1, d1, fmaf(d2, d2, d3 * d3)));
    }
    float2 S = block_sum2(a1, a2, s_red2, &s_bc2);
    float var = (S.y - S.x * S.x * (1.0f / NPIX)) * (1.0f / (NPIX - 1));
    float inv_std = 1.0f / (sqrtf(fmaxf(var, 0.f)) + 1e-6f);

    // ---- Phase B: gate + q (dL recomputed from own-pixel registers) ----
    float Ln = 0.299f * rr + 0.587f * gg + 0.114f * bb;
    float dL = fabsf(Ln - mu);
    float gate = 1.0f / (1.0f + ex2f(-dL * inv_std * LOG2E));
    float gf = 1.0f + gate;

    float q = (wq0 * rr + wq1 * gg + wq2 * bb) * gf;

    // bin geometry from wk row (exact bounds: rgb in [0,1])
    float mn = fminf(w0, 0.f) + fminf(w1, 0.f) + fminf(w2, 0.f);
    float mx = fmaxf(w0, 0.f) + fmaxf(w1, 0.f) + fmaxf(w2, 0.f);
    float kmin2 = mn * LOG2E;
    float delta = (mx - mn) * (LOG2E / NBINS);
    if (delta < 1e-20f) delta = 1e-20f;
    float cen0 = kmin2 + 0.5f * delta;

    if (half == 0) {
        float k = (w0 * rr + w1 * gg + w2 * bb);
        float v = (wv0 * rr + wv1 * gg + wv2 * bb);
        float k2 = k * LOG2E;
        int j = (int)((k2 - kmin2) * (1.0f / delta));
        j = max(0, min(NBINS - 1, j));
        float d2 = k2 - fmaf((float)j, delta, cen0);
        float4* mp = &g_mom4[pb][b * CH + ch][j][0];
        red_v4(mp, v, v * d2, v * d2 * d2, 1.0f);
        red_v2(mp + 1, d2, d2 * d2);
    }

    // ---- per-batch grid barrier (32 blocks), acq/rel scoped ----
    __syncthreads();
    if (t == 0) {
        if (atom_add_acqrel(&g_cnt[b], 1) == BPB - 1) {
            asm volatile("st.relaxed.gpu.global.u32 [%0], %1;" :: "l"(&g_cnt[b]), "r"(0u) : "memory");
            red_add_release(&g_gen[b], 1);
        } else {
            while (ld_acquire(&g_gen[b]) == gen0) { }
        }
    }
    __syncthreads();

    // ---- Phase C: load moments, evaluate (split bins), combine, output ----
    {
        const float4* gm4 = &g_mom4[pb][b * CH][0][0];
        if (t < CH * NBINS * 2) s_mom[t] = __ldcg(&gm4[t]);
    }
    __syncthreads();

    float u = q * LN2;
    float h2 = 0.5f * u * u;
    float step = q * delta;
    float c0 = q * cen0;
    float cL = fmaf((float)(NBINS - 1), step, c0);
    float offs = -fmaxf(c0, cL);                        // global row max
    float arg = fmaf((float)(half * HBINS), step, c0) + offs;
    float step2 = step + step;

    float n0 = 0.f, n1 = 0.f, d0a = 0.f, d1a = 0.f;
    const float4* sp = s_mom + (ch * NBINS + half * HBINS) * 2;

    #pragma unroll 8
    for (int jj = 0; jj < HBINS * 2; jj += 4) {
        float4 A0 = sp[jj],     B0 = sp[jj + 1];
        float4 A1 = sp[jj + 2], B1 = sp[jj + 3];
        float e0 = ex2f(arg);
        float e1 = ex2f(arg + step);
        arg += step2;
        float pn0 = fmaf(h2, A0.z, fmaf(u, A0.y, A0.x));
        float pd0 = fmaf(h2, B0.y, fmaf(u, B0.x, A0.w));
        n0 = fmaf(e0, pn0, n0);
        d0a = fmaf(e0, pd0, d0a);
        float pn1 = fmaf(h2, A1.z, fmaf(u, A1.y, A1.x));
        float pd1 = fmaf(h2, B1.y, fmaf(u, B1.x, A1.w));
        n1 = fmaf(e1, pn1, n1);
        d1a = fmaf(e1, pd1, d1a);
    }
    s_nd[t] = make_float2(n0 + n1, d0a + d1a);
    __syncthreads();

    // t<128 (ch=0, half=0) combines all three channels directly and writes out
    if (t < 128) {
        float px[3] = {rr, gg, bb};
        #pragma unroll
        for (int c = 0; c < 3; c++) {
            int tk = (c << 7) + t;
            float2 lo = s_nd[tk], hi = s_nd[tk + 384];
            float att = __fdividef(lo.x + hi.x, lo.y + hi.y);
            px[0] = fmaf(wo[3 * 0 + c], att, (c == 0) ? px[0] : px[0]);
            // accumulate per output channel below instead
            s_red[0] = s_red[0];  // no-op to keep structure clear
            // store att for reuse
            ((float*)s_red2)[c] = 0.f;  // unused
            // write handled after loop via atts[]
            ((float*)&s_bc2)[0] = ((float*)&s_bc2)[0];
            // (see atts accumulation below)
            if (c == 0) { s_nd[t].x = att; }
            else if (c == 1) { s_nd[t].y = att; }
            else { s_nd[128 + t].x = att; }
        }
        float a0 = s_nd[t].x;
        float a1o = s_nd[t].y;
        float a2o = s_nd[128 + t].x;
        float pr[3] = {rr, gg, bb};
        #pragma unroll
        for (int c = 0; c < 3; c++) {
            float o = wo[3 * c] * a0 + wo[3 * c + 1] * a1o + wo[3 * c + 2] * a2o;
            size_t off = ((size_t)b * CH + c) * NPIX + n;
            float val = pr[c] + o;
            out[off] = fminf(fmaxf(val, 0.f), 1.f);
        }
    }
}

extern "C" void kernel_launch(void* const* d_in, const int* in_sizes, int n_in,
                              void* d_out, int out_size)
{
    const float* rgb = (const float*)d_in[0];
    const float* wq  = (const float*)d_in[1];
    const float* wk  = (const float*)d_in[2];
    const float* wv  = (const float*)d_in[3];
    const float* wo  = (const float*)d_in[4];
    float* out = (float*)d_out;

    fused_kernel<<<GRID, NTHR>>>(rgb, wq, wk, wv, wo, out);
}